// round 16
// baseline (speedup 1.0000x reference)
#include <cuda_runtime.h>
#include <cuda_fp16.h>
#include <math.h>
#include <stdint.h>

#define W_IMG 128
#define NB 16
#define LDA 40      // A smem stride in halves
#define LDB 168     // B smem stride in halves (21*16B rows -> conflict-free ldmatrix)
#define NTILE 160   // CTA N tile (exact divisor of 160/320/640)
#define THREADS 320 // 10 warps: 2(M) x 5(N)

// ---------------- scratch (static device globals; no allocation) ----------------
__device__ __half g_convh[41943040];  // conv output per stage (fp16)
__device__ float  g_pool[20971520];   // stage-1 input data
__device__ float  g_maskA[524288];    // stage input mask (N,1,H,W)
__device__ float  g_maskB[524288];    // full-res mask_next before pooling
__device__ float  g_stats[1280];      // [sum(0..C), sumsq(C..2C)]
__device__ __half g_wTh[1843200];     // transposed fp16 weights [tap][ciP][Cout]
__device__ __half g_xmh[25165824];    // fp16 premasked transposed input [n][h][w][ciP]
__device__ float  g_feat[NB * 640];
__device__ float  g_z1[NB * 256];
__device__ float  g_z2[NB * 128];

__device__ __forceinline__ uint32_t smem_u32(const void* p) {
    uint32_t a;
    asm("{ .reg .u64 t; cvta.to.shared.u64 t, %1; cvt.u32.u64 %0, t; }" : "=r"(a) : "l"(p));
    return a;
}
__device__ __forceinline__ void cpa16(uint32_t dst, const void* src, uint32_t sz) {
    asm volatile("cp.async.cg.shared.global [%0], [%1], 16, %2;"
                 :: "r"(dst), "l"(src), "r"(sz) : "memory");
}
#define CP_COMMIT() asm volatile("cp.async.commit_group;" ::: "memory")
#define CP_WAIT1()  asm volatile("cp.async.wait_group 1;" ::: "memory")

#define LDMX4(r0, r1, r2, r3, addr) \
    asm volatile("ldmatrix.sync.aligned.m8n8.x4.shared.b16 {%0,%1,%2,%3}, [%4];" \
                 : "=r"(r0), "=r"(r1), "=r"(r2), "=r"(r3) : "r"(addr))
#define LDMX2T(r0, r1, addr) \
    asm volatile("ldmatrix.sync.aligned.m8n8.x2.trans.shared.b16 {%0,%1}, [%2];" \
                 : "=r"(r0), "=r"(r1) : "r"(addr))
#define MMA16816(d, a, b) \
    asm volatile("mma.sync.aligned.m16n8k16.row.col.f32.f16.f16.f32 " \
                 "{%0,%1,%2,%3}, {%4,%5,%6,%7}, {%8,%9}, {%0,%1,%2,%3};" \
                 : "+f"((d)[0]), "+f"((d)[1]), "+f"((d)[2]), "+f"((d)[3]) \
                 : "r"((a)[0]), "r"((a)[1]), "r"((a)[2]), "r"((a)[3]), \
                   "r"((b)[0]), "r"((b)[1]))

// dynamic smem layout (bytes)
// A: per chunk-slot 2 h-row tiles of 132 x LDA halves; double-buffered.
#define ATILE   (132 * LDA * 2)          // 10560 per h-row tile
#define ABUF2   (2 * ATILE)              // 21120 per slot
#define OFF_A   0
#define OFF_B   (2 * ABUF2)              // 42240
#define BBUF    (32 * LDB * 2)           // 10752
#define OFF_M   (OFF_B + 3 * BBUF)       // 74496 ; mask 4x132 f
#define OFF_SC  (OFF_M + 2112)           // 76608 ; 256 f
#define OFF_NV  (OFF_SC + 1024)          // 77632 ; 256 f
#define OFF_BI  (OFF_NV + 1024)          // 78656 ; 160 f
#define SM_TOT  (OFF_BI + 640)           // 79296  (2 CTAs/SM: 158.6KB < 228KB)

// ---------------- prep: split data / clipped mask ----------------
__global__ void prep_kernel(const float* __restrict__ x) {
    int idx = blockIdx.x * blockDim.x + threadIdx.x;
    const int per = 256 * 128;
    if (idx >= NB * per) return;
    int n = idx / per;
    int rest = idx - n * per;
    g_pool[idx] = x[(n * 2 + 0) * per + rest];
    float m = x[(n * 2 + 1) * per + rest];
    g_maskA[idx] = fminf(fmaxf(m, 0.f), 1.f);
}

__global__ void zero_stats_kernel(int n) {
    int i = blockIdx.x * blockDim.x + threadIdx.x;
    if (i < n) g_stats[i] = 0.f;
}

// ---------------- weight transpose: wts[co][ci][tap] -> g_wTh[tap][ciP][Cout] ----------------
__global__ void wprep_kernel(const float* __restrict__ wts,
                             int Cin, int Cinp, int Cout) {
    int idx = blockIdx.x * blockDim.x + threadIdx.x;
    int total = 9 * Cinp * Cout;
    if (idx >= total) return;
    int tap = idx / (Cinp * Cout);
    int rem = idx - tap * (Cinp * Cout);
    int ci = rem / Cout;
    int co = rem - ci * Cout;
    float v = 0.f;
    if (ci < Cin) v = wts[(co * Cin + ci) * 9 + tap];
    g_wTh[idx] = __float2half(v);
}

// ---------------- stage-1 partial conv, specialized Cin=1, Cout=80 ----------------
__launch_bounds__(256)
__global__ void pconv1_kernel(const float* __restrict__ wts,
                              const float* __restrict__ bias,
                              int H)
{
    __shared__ float s_m[3][132];
    __shared__ float s_in[3][132];
    __shared__ float s_w[9][80];

    const int t    = threadIdx.x;
    const int h    = blockIdx.x;
    const int n    = blockIdx.y;
    const int pxg  = t & 31;
    const int cog  = t >> 5;
    const int px0  = pxg * 4;
    const int lane = t & 31;

    for (int idx = t; idx < 3 * 130; idx += 256) {
        int r = idx / 130, col = idx % 130;
        int hh = h - 1 + r, ww = col - 1;
        float mv = 1.0f, dv = 0.f;
        if (hh >= 0 && hh < H && ww >= 0 && ww < W_IMG) {
            mv = g_maskA[(n * H + hh) * W_IMG + ww];
            dv = g_pool[(n * H + hh) * W_IMG + ww] * mv;
        }
        s_m[r][col]  = mv;
        s_in[r][col] = dv;
    }
    for (int idx = t; idx < 720; idx += 256)
        s_w[idx / 80][idx % 80] = wts[(idx % 80) * 9 + idx / 80];
    __syncthreads();

    float msum[4];
    #pragma unroll
    for (int p = 0; p < 4; p++) {
        float s = 0.f;
        #pragma unroll
        for (int r = 0; r < 3; r++)
            #pragma unroll
            for (int tw = 0; tw < 3; tw++)
                s += s_m[r][px0 + p + tw];
        msum[p] = s;
    }

    float acc[10][4];
    #pragma unroll
    for (int j = 0; j < 10; j++)
        #pragma unroll
        for (int p = 0; p < 4; p++) acc[j][p] = 0.f;

    #pragma unroll
    for (int r = 0; r < 3; r++) {
        float iv[6];
        #pragma unroll
        for (int k = 0; k < 6; k++) iv[k] = s_in[r][px0 + k];
        #pragma unroll
        for (int tw = 0; tw < 3; tw++) {
            #pragma unroll
            for (int j = 0; j < 10; j++) {
                float wj = s_w[r * 3 + tw][cog * 10 + j];
                #pragma unroll
                for (int p = 0; p < 4; p++)
                    acc[j][p] += wj * iv[tw + p];
            }
        }
    }

    float scale[4];
    bool  nov[4];
    #pragma unroll
    for (int p = 0; p < 4; p++) {
        float valid = msum[p];
        nov[p]   = (valid <= 0.f);
        scale[p] = 9.0f / fmaxf(valid, 1.0f);
    }
    if (cog == 0) {
        #pragma unroll
        for (int p = 0; p < 4; p++)
            g_maskB[(n * H + h) * W_IMG + px0 + p] = nov[p] ? 0.f : 1.f;
    }

    #pragma unroll
    for (int j = 0; j < 10; j++) {
        int gco = cog * 10 + j;
        float b = bias[gco];
        float ssum = 0.f, ssq = 0.f;
        #pragma unroll
        for (int p = 0; p < 4; p++) {
            float y = nov[p] ? 0.f : (acc[j][p] * scale[p] + b);
            g_convh[((size_t)(n * 80 + gco) * H + h) * W_IMG + px0 + p] = __float2half(y);
            ssum += y;
            ssq  += y * y;
        }
        #pragma unroll
        for (int off = 16; off; off >>= 1) {
            ssum += __shfl_xor_sync(0xffffffffu, ssum, off);
            ssq  += __shfl_xor_sync(0xffffffffu, ssq,  off);
        }
        if (lane == 0) {
            atomicAdd(&g_stats[gco], ssum);
            atomicAdd(&g_stats[80 + gco], ssq);
        }
    }
}

// ---------------- fp16 HMMA implicit-GEMM partial conv, 2 output rows per CTA ----------------
// Per chunk: load B once, run MMA block for h0 and h0+1 (B L2 traffic halved).
// A tile per (r, ci0, hr); taps sc=0..2 read at row offset sc. TAIL: last ci
// chunk of each tap is 16-wide (stage 2, Cinp=80). TAIL=false is branch-free.
template <bool TAIL>
__launch_bounds__(THREADS, 2)
__global__ void pconv_hmma_kernel(const float* __restrict__ bias,
                                  int Cin, int Cinp, int Cout, int H)
{
    extern __shared__ char smem[];
    const uint32_t sb = smem_u32(smem);
    float* s_m  = (float*)(smem + OFF_M);
    float* s_sc = (float*)(smem + OFF_SC);
    float* s_nv = (float*)(smem + OFF_NV);
    float* s_bi = (float*)(smem + OFF_BI);

    const int t    = threadIdx.x;
    const int wid  = t >> 5;
    const int lane = t & 31;
    const int H2   = H >> 1;
    const int h0   = (blockIdx.x % H2) * 2;
    const int n    = blockIdx.x / H2;
    const int co0  = blockIdx.y * NTILE;
    const int warp_m = wid & 1;
    const int warp_n = wid >> 1;

    // mask rows h0-1 .. h0+2 (OOB = 1.0) + bias
    for (int idx = t; idx < 4 * 130; idx += THREADS) {
        int r = idx / 130, col = idx % 130;
        int hh = h0 - 1 + r, ww = col - 1;
        float v = 1.0f;
        if (hh >= 0 && hh < H && ww >= 0 && ww < W_IMG)
            v = g_maskA[(n * H + hh) * W_IMG + ww];
        s_m[r * 132 + col] = v;
    }
    if (t < NTILE) s_bi[t] = bias[co0 + t];
    __syncthreads();

    // scale / no-valid / mask_next for 256 output px (2 rows)
    if (t < 256) {
        int hi = t >> 7, w = t & 127;
        float s = 0.f;
        #pragma unroll
        for (int r = 0; r < 3; r++)
            #pragma unroll
            for (int tw = 0; tw < 3; tw++)
                s += s_m[(hi + r) * 132 + w + tw];
        float valid = (float)Cin * s;
        s_nv[t] = (valid <= 0.f) ? 1.f : 0.f;
        s_sc[t] = (float)(Cin * 9) / fmaxf(valid, 1.0f);
        if (blockIdx.y == 0)
            g_maskB[(n * H + h0 + hi) * W_IMG + w] = (valid <= 0.f) ? 0.f : 1.f;
    }
    __syncthreads();

    const int CPT = (Cinp + 31) >> 5;   // ci chunks per tap (last may be 16 when TAIL)
    const int chunks = 9 * CPT;         // (r, j, sc) with sc fastest

    auto issue = [&](int c) {
        int sc = c % 3;
        int rem = c / 3;
        int j = rem % CPT;
        int r = rem / CPT;
        int ci0 = j << 5;
        int tap = r * 3 + sc;
        const bool is16 = TAIL && (j == CPT - 1);
        // B: shared across both h rows
        const __half* wsrc = g_wTh + ((size_t)tap * Cinp + ci0) * Cout + co0;
        const uint32_t bbase = sb + OFF_B + (c % 3) * BBUF;
        if (!is16) {
            #pragma unroll
            for (int i = 0; i < 2; i++) {
                int op = t + i * THREADS;
                int k = op / 20, seg = op - k * 20;
                cpa16(bbase + k * LDB * 2 + seg * 16, wsrc + (size_t)k * Cout + seg * 8, 16u);
            }
        } else {
            int k = t / 20, seg = t - (t / 20) * 20;
            if (k < 16)
                cpa16(bbase + k * LDB * 2 + seg * 16, wsrc + (size_t)k * Cout + seg * 8, 16u);
        }
        if (sc == 0) {
            // A: 2 h-row tiles of 132 rows; writes go to buffer (rem+1)&1 parity-safe
            const uint32_t abase = sb + OFF_A + (rem & 1) * ABUF2;
            if (!is16) {
                // 2 x 528 = 1056 ops, 4 segs of 16B per px row
                #pragma unroll
                for (int i = 0; i < 4; i++) {
                    int op = t + i * THREADS;
                    if (op < 1056) {
                        int hr = (op >= 528) ? 1 : 0;
                        int opp = op - hr * 528;
                        int p = opp >> 2, seg = opp & 3;
                        int hh = h0 + hr - 1 + r;
                        int ww = p - 1;
                        bool ok = (hh >= 0 && hh < H) && ((unsigned)ww < W_IMG);
                        const __half* src = ok
                            ? &g_xmh[((size_t)(n * H + hh) * W_IMG + ww) * Cinp + ci0 + seg * 8]
                            : g_xmh;
                        cpa16(abase + hr * ATILE + (p * LDA + seg * 8) * 2, src, ok ? 16u : 0u);
                    }
                }
            } else {
                // 2 x 264 = 528 ops, 2 segs of 16B per px row
                #pragma unroll
                for (int i = 0; i < 2; i++) {
                    int op = t + i * THREADS;
                    if (op < 528) {
                        int hr = (op >= 264) ? 1 : 0;
                        int opp = op - hr * 264;
                        int p = opp >> 1, seg = opp & 1;
                        int hh = h0 + hr - 1 + r;
                        int ww = p - 1;
                        bool ok = (hh >= 0 && hh < H) && ((unsigned)ww < W_IMG);
                        const __half* src = ok
                            ? &g_xmh[((size_t)(n * H + hh) * W_IMG + ww) * Cinp + ci0 + seg * 8]
                            : g_xmh;
                        cpa16(abase + hr * ATILE + (p * LDA + seg * 8) * 2, src, ok ? 16u : 0u);
                    }
                }
            }
        }
        CP_COMMIT();
    };

    float acc[2][4][4][4];
    #pragma unroll
    for (int hr = 0; hr < 2; hr++)
        #pragma unroll
        for (int mi = 0; mi < 4; mi++)
            #pragma unroll
            for (int ni = 0; ni < 4; ni++)
                #pragma unroll
                for (int q = 0; q < 4; q++) acc[hr][mi][ni][q] = 0.f;

    const int rowX = lane & 15;
    const int colA = (lane >> 4) << 3;
    const uint32_t a_rel = ((warp_m * 64 + rowX) * LDA + colA) * 2;
    const uint32_t b_rel = (rowX * LDB + warp_n * 32) * 2;

    issue(0);
    if (chunks > 1) issue(1);

    for (int c = 0; c < chunks; c++) {
        CP_WAIT1();
        __syncthreads();          // single barrier per chunk
        if (c + 2 < chunks) issue(c + 2);

        const int sc = c % 3;
        const int rem = c / 3;
        const uint32_t abase0 = sb + OFF_A + (rem & 1) * ABUF2 + sc * LDA * 2 + a_rel;
        const uint32_t bbase  = sb + OFF_B + (c % 3) * BBUF + b_rel;
        const int kmax = (TAIL && (rem % CPT == CPT - 1)) ? 1 : 2;

        #pragma unroll
        for (int kk = 0; kk < 2; kk++) {
            if (!TAIL || kk < kmax) {
                uint32_t b[4][2];
                #pragma unroll
                for (int ni = 0; ni < 4; ni++)
                    LDMX2T(b[ni][0], b[ni][1],
                           bbase + (kk * 16 * LDB + ni * 8) * 2);
                #pragma unroll
                for (int hr = 0; hr < 2; hr++) {
                    const uint32_t abase = abase0 + hr * ATILE;
                    #pragma unroll
                    for (int mi = 0; mi < 4; mi++) {
                        uint32_t a[4];
                        LDMX4(a[0], a[1], a[2], a[3],
                              abase + (mi * 16 * LDA + kk * 16) * 2);
                        #pragma unroll
                        for (int ni = 0; ni < 4; ni++)
                            MMA16816(acc[hr][mi][ni], a, b[ni]);
                    }
                }
            }
        }
    }
    __syncthreads();

    // ---- epilogue: scale/bias/zero + fp16 stores + stats ----
    const int gr = lane >> 2;
    const int gc = (lane & 3) * 2;
    float ssum[4][2], ssq[4][2];
    #pragma unroll
    for (int ni = 0; ni < 4; ni++)
        #pragma unroll
        for (int q = 0; q < 2; q++) { ssum[ni][q] = 0.f; ssq[ni][q] = 0.f; }

    #pragma unroll
    for (int hr = 0; hr < 2; hr++) {
        const int h = h0 + hr;
        #pragma unroll
        for (int mi = 0; mi < 4; mi++) {
            int m0 = warp_m * 64 + mi * 16 + gr;
            int m1 = m0 + 8;
            float sc0 = s_sc[hr * 128 + m0], sc1 = s_sc[hr * 128 + m1];
            bool nv0 = (s_nv[hr * 128 + m0] != 0.f), nv1 = (s_nv[hr * 128 + m1] != 0.f);
            #pragma unroll
            for (int ni = 0; ni < 4; ni++) {
                int colb = warp_n * 32 + ni * 8 + gc;
                #pragma unroll
                for (int q = 0; q < 2; q++) {
                    int col = colb + q;
                    int co = co0 + col;
                    float bb = s_bi[col];
                    float y0 = nv0 ? 0.f : fmaf(acc[hr][mi][ni][q], sc0, bb);
                    float y1 = nv1 ? 0.f : fmaf(acc[hr][mi][ni][2 + q], sc1, bb);
                    size_t base = ((size_t)(n * Cout + co) * H + h) * W_IMG;
                    g_convh[base + m0] = __float2half(y0);
                    g_convh[base + m1] = __float2half(y1);
                    ssum[ni][q] += y0 + y1;
                    ssq[ni][q]  += y0 * y0 + y1 * y1;
                }
            }
        }
    }
    #pragma unroll
    for (int ni = 0; ni < 4; ni++)
        #pragma unroll
        for (int q = 0; q < 2; q++) {
            float ss = ssum[ni][q], sq = ssq[ni][q];
            #pragma unroll
            for (int off = 4; off <= 16; off <<= 1) {
                ss += __shfl_xor_sync(0xffffffffu, ss, off);
                sq += __shfl_xor_sync(0xffffffffu, sq, off);
            }
            if (lane < 4) {
                int co = co0 + warp_n * 32 + ni * 8 + lane * 2 + q;
                atomicAdd(&g_stats[co], ss);
                atomicAdd(&g_stats[Cout + co], sq);
            }
        }
}

// ---------------- fused BN+ReLU+pool+premask+transpose+fp16: conv -> g_xmh ----------------
__global__ void bnx_kernel(const float* __restrict__ gamma,
                           const float* __restrict__ beta,
                           int Cout, int Hc, int Cinp)
{
    __shared__ __half tile[32][33];
    int Hp = Hc >> 1;
    int nhp = blockIdx.z;
    int n = nhp / Hp, hp = nhp % Hp;
    int w0 = blockIdx.x * 32, c0 = blockIdx.y * 32;
    int tx = threadIdx.x, ty = threadIdx.y;

    float m = g_maskA[nhp * W_IMG + w0 + tx];
    float cnt = (float)(NB * Hc * W_IMG);

    #pragma unroll
    for (int j = 0; j < 4; j++) {
        int cl = ty + j * 8;
        int c = c0 + cl;
        float y = 0.f;
        if (c < Cout) {
            float mean = g_stats[c] / cnt;
            float var  = g_stats[Cout + c] / cnt - mean * mean;
            float inv  = rsqrtf(var + 1e-5f);
            float ga = gamma[c], bb = beta[c];
            size_t base = ((size_t)(n * Cout + c) * Hc + 2 * hp) * W_IMG + w0 + tx;
            float v0 = __half2float(g_convh[base]);
            float v1 = __half2float(g_convh[base + W_IMG]);
            float r0 = fmaxf((v0 - mean) * inv * ga + bb, 0.f);
            float r1 = fmaxf((v1 - mean) * inv * ga + bb, 0.f);
            y = fmaxf(r0, r1) * m;
        }
        tile[cl][tx] = __float2half(y);
    }
    __syncthreads();
    if (c0 + tx < Cinp) {
        #pragma unroll
        for (int j = 0; j < 4; j++) {
            int wl = ty + j * 8;
            g_xmh[((size_t)nhp * W_IMG + w0 + wl) * Cinp + c0 + tx] = tile[tx][wl];
        }
    }
}

// ---------------- fused stage-4 BN+ReLU+pool+mean -> g_feat ----------------
__global__ void bnfeat_kernel(const float* __restrict__ gamma,
                              const float* __restrict__ beta,
                              int Cout, int Hc)
{
    __shared__ float sred[128];
    int c = blockIdx.x % Cout;
    int n = blockIdx.x / Cout;
    int t = threadIdx.x;
    int Hp = Hc >> 1;

    float cnt  = (float)(NB * Hc * W_IMG);
    float mean = g_stats[c] / cnt;
    float var  = g_stats[Cout + c] / cnt - mean * mean;
    float inv  = rsqrtf(var + 1e-5f);
    float ga = gamma[c], bb = beta[c];

    float s = 0.f;
    for (int i = t; i < Hp * W_IMG; i += 128) {
        int hp = i >> 7, w = i & 127;
        size_t base = ((size_t)(n * Cout + c) * Hc + 2 * hp) * W_IMG + w;
        float v0 = __half2float(g_convh[base]);
        float v1 = __half2float(g_convh[base + W_IMG]);
        float r0 = fmaxf((v0 - mean) * inv * ga + bb, 0.f);
        float r1 = fmaxf((v1 - mean) * inv * ga + bb, 0.f);
        s += fmaxf(r0, r1);
    }
    sred[t] = s;
    __syncthreads();
    for (int o = 64; o; o >>= 1) {
        if (t < o) sred[t] += sred[t + o];
        __syncthreads();
    }
    if (t == 0) g_feat[n * Cout + c] = sred[0] / (float)(Hp * W_IMG);
}

__global__ void mask_pool_kernel(int Hc) {
    int idx = blockIdx.x * blockDim.x + threadIdx.x;
    int Hp = Hc >> 1;
    int total = NB * Hp * W_IMG;
    if (idx >= total) return;
    int w  = idx % W_IMG;
    int hp = (idx / W_IMG) % Hp;
    int n  = idx / (W_IMG * Hp);
    int base = (n * Hc + 2 * hp) * W_IMG + w;
    g_maskA[(n * Hp + hp) * W_IMG + w] = fmaxf(g_maskB[base], g_maskB[base + W_IMG]);
}

// ---------------- head ----------------
__global__ void fc_kernel(const float* __restrict__ Wm, const float* __restrict__ b,
                          const float* __restrict__ in, float* __restrict__ out,
                          int IN, int OUT, int act)
{
    __shared__ float s[640];
    int n = blockIdx.x;
    for (int i = threadIdx.x; i < IN; i += blockDim.x) s[i] = in[n * IN + i];
    __syncthreads();
    int o = threadIdx.x;
    if (o < OUT) {
        float a = b[o];
        const float* wr = Wm + o * IN;
        for (int k = 0; k < IN; k++) a += wr[k] * s[k];
        if (act == 0) a = fmaxf(a, 0.f);
        else          a = 1.f / (1.f + expf(-a));
        out[n * OUT + o] = a;
    }
}

// ---------------- launch ----------------
extern "C" void kernel_launch(void* const* d_in, const int* in_sizes, int n_in,
                              void* d_out, int out_size)
{
    const float* x = (const float*)d_in[0];
    const float* w[4]  = {(const float*)d_in[1],  (const float*)d_in[5],
                          (const float*)d_in[9],  (const float*)d_in[13]};
    const float* bi[4] = {(const float*)d_in[2],  (const float*)d_in[6],
                          (const float*)d_in[10], (const float*)d_in[14]};
    const float* ga[4] = {(const float*)d_in[3],  (const float*)d_in[7],
                          (const float*)d_in[11], (const float*)d_in[15]};
    const float* be[4] = {(const float*)d_in[4],  (const float*)d_in[8],
                          (const float*)d_in[12], (const float*)d_in[16]};
    const float* fw1 = (const float*)d_in[17];
    const float* fb1 = (const float*)d_in[18];
    const float* fw2 = (const float*)d_in[19];
    const float* fb2 = (const float*)d_in[20];
    const float* hw  = (const float*)d_in[21];
    const float* hb  = (const float*)d_in[22];

    cudaFuncSetAttribute(pconv_hmma_kernel<true>,
                         cudaFuncAttributeMaxDynamicSharedMemorySize, SM_TOT);
    cudaFuncSetAttribute(pconv_hmma_kernel<false>,
                         cudaFuncAttributeMaxDynamicSharedMemorySize, SM_TOT);

    float *feat, *z1, *z2;
    cudaGetSymbolAddress((void**)&feat, g_feat);
    cudaGetSymbolAddress((void**)&z1,   g_z1);
    cudaGetSymbolAddress((void**)&z2,   g_z2);

    prep_kernel<<<(NB * 256 * 128 + 255) / 256, 256>>>(x);

    // ---- stage 1: specialized Cin=1 -> fused bnx into g_xmh (Cinp=80, exact) ----
    {
        int Cout = 80, H = 256, Hp = 128;
        zero_stats_kernel<<<1, 256>>>(2 * Cout);
        dim3 grid(H, NB);
        pconv1_kernel<<<grid, 256>>>(w[0], bi[0], H);
        mask_pool_kernel<<<(NB * Hp * W_IMG + 255) / 256, 256>>>(H);
        dim3 bg(4, 3, NB * Hp);   // c0 = 0,32,64 covering 80 (store-guarded)
        bnx_kernel<<<bg, dim3(32, 8)>>>(ga[0], be[0], Cout, H, 80);
    }

    // ---- stages 2-4: fp16 HMMA implicit GEMM, exact M/N/K, 2 rows/CTA ----
    int Cin = 80, H = 128;
    const int Couts[3] = {160, 320, 640};
    for (int s = 0; s < 3; s++) {
        int Cout = Couts[s];
        int Cinp = (Cin + 15) & ~15;   // 80, 160, 320
        int nT = Cout / NTILE;

        int wtot = 9 * Cinp * Cout;
        wprep_kernel<<<(wtot + 255) / 256, 256>>>(w[s + 1], Cin, Cinp, Cout);
        zero_stats_kernel<<<(2 * Cout + 255) / 256, 256>>>(2 * Cout);

        dim3 grid(NB * (H / 2), nT);
        if (Cinp & 31)
            pconv_hmma_kernel<true><<<grid, THREADS, SM_TOT>>>(bi[s + 1], Cin, Cinp, Cout, H);
        else
            pconv_hmma_kernel<false><<<grid, THREADS, SM_TOT>>>(bi[s + 1], Cin, Cinp, Cout, H);

        int Hp = H / 2;
        if (s < 2) {
            mask_pool_kernel<<<(NB * Hp * W_IMG + 255) / 256, 256>>>(H);
            int CinpN = Cout;          // 160, 320 — exact
            dim3 bg(4, (CinpN + 31) / 32, NB * Hp);
            bnx_kernel<<<bg, dim3(32, 8)>>>(ga[s + 1], be[s + 1], Cout, H, CinpN);
        } else {
            bnfeat_kernel<<<NB * Cout, 128>>>(ga[s + 1], be[s + 1], Cout, H);
        }
        Cin = Cout; H = Hp;
    }

    fc_kernel<<<NB, 256>>>(fw1, fb1, feat, z1, 640, 256, 0);
    fc_kernel<<<NB, 256>>>(fw2, fb2, z1, z2, 256, 128, 0);
    fc_kernel<<<NB, 128>>>(hw, hb, z2, (float*)d_out, 128, 1, 1);
}

// round 17
// speedup vs baseline: 3.2392x; 3.2392x over previous
#include <cuda_runtime.h>
#include <cuda_fp16.h>
#include <math.h>
#include <stdint.h>

#define W_IMG 128
#define NB 16
#define LDA 40      // A smem stride in halves
#define LDB 168     // B smem stride in halves (21*16B rows -> conflict-free ldmatrix)
#define NTILE 160   // CTA N tile (exact divisor of 160/320/640)
#define THREADS 320 // 10 warps: 2(M) x 5(N)

// ---------------- scratch (static device globals; no allocation) ----------------
__device__ __half g_convh[41943040];  // conv output per stage (fp16)
__device__ float  g_pool[20971520];   // stage-1 input data
__device__ float  g_maskA[524288];    // stage input mask (N,1,H,W)
__device__ float  g_maskB[524288];    // full-res mask_next before pooling
__device__ float  g_stats[1280];      // [sum(0..C), sumsq(C..2C)]
__device__ __half g_wTh[1843200];     // transposed fp16 weights [tap][ciP][Cout]
__device__ __half g_xmh[25165824];    // fp16 premasked transposed input [n][h][w][ciP]
__device__ float  g_feat[NB * 640];
__device__ float  g_z1[NB * 256];
__device__ float  g_z2[NB * 128];

__device__ __forceinline__ uint32_t smem_u32(const void* p) {
    uint32_t a;
    asm("{ .reg .u64 t; cvta.to.shared.u64 t, %1; cvt.u32.u64 %0, t; }" : "=r"(a) : "l"(p));
    return a;
}
__device__ __forceinline__ void cpa16(uint32_t dst, const void* src, uint32_t sz) {
    asm volatile("cp.async.cg.shared.global [%0], [%1], 16, %2;"
                 :: "r"(dst), "l"(src), "r"(sz) : "memory");
}
#define CP_COMMIT() asm volatile("cp.async.commit_group;" ::: "memory")
#define CP_WAIT1()  asm volatile("cp.async.wait_group 1;" ::: "memory")

#define LDMX4(r0, r1, r2, r3, addr) \
    asm volatile("ldmatrix.sync.aligned.m8n8.x4.shared.b16 {%0,%1,%2,%3}, [%4];" \
                 : "=r"(r0), "=r"(r1), "=r"(r2), "=r"(r3) : "r"(addr))
#define LDMX2T(r0, r1, addr) \
    asm volatile("ldmatrix.sync.aligned.m8n8.x2.trans.shared.b16 {%0,%1}, [%2];" \
                 : "=r"(r0), "=r"(r1) : "r"(addr))
#define MMA16816(d, a, b) \
    asm volatile("mma.sync.aligned.m16n8k16.row.col.f32.f16.f16.f32 " \
                 "{%0,%1,%2,%3}, {%4,%5,%6,%7}, {%8,%9}, {%0,%1,%2,%3};" \
                 : "+f"((d)[0]), "+f"((d)[1]), "+f"((d)[2]), "+f"((d)[3]) \
                 : "r"((a)[0]), "r"((a)[1]), "r"((a)[2]), "r"((a)[3]), \
                   "r"((b)[0]), "r"((b)[1]))

// dynamic smem layout (bytes)
#define OFF_A   0
#define ABUF    (132 * LDA * 2)          // 10560
#define OFF_B   (2 * ABUF)               // 21120
#define BBUF    (32 * LDB * 2)           // 10752
#define OFF_M   (OFF_B + 3 * BBUF)       // 53376
#define OFF_SC  (OFF_M + 1584)           // 54960
#define OFF_NV  (OFF_SC + 512)           // 55472
#define OFF_BI  (OFF_NV + 512)           // 55984
#define SM_TOT  (OFF_BI + 640)           // 56624

// ---------------- prep: split data / clipped mask ----------------
__global__ void prep_kernel(const float* __restrict__ x) {
    int idx = blockIdx.x * blockDim.x + threadIdx.x;
    const int per = 256 * 128;
    if (idx >= NB * per) return;
    int n = idx / per;
    int rest = idx - n * per;
    g_pool[idx] = x[(n * 2 + 0) * per + rest];
    float m = x[(n * 2 + 1) * per + rest];
    g_maskA[idx] = fminf(fmaxf(m, 0.f), 1.f);
}

__global__ void zero_stats_kernel(int n) {
    int i = blockIdx.x * blockDim.x + threadIdx.x;
    if (i < n) g_stats[i] = 0.f;
}

// ---------------- weight transpose: wts[co][ci][tap] -> g_wTh[tap][ciP][Cout] ----------------
__global__ void wprep_kernel(const float* __restrict__ wts,
                             int Cin, int Cinp, int Cout) {
    int idx = blockIdx.x * blockDim.x + threadIdx.x;
    int total = 9 * Cinp * Cout;
    if (idx >= total) return;
    int tap = idx / (Cinp * Cout);
    int rem = idx - tap * (Cinp * Cout);
    int ci = rem / Cout;
    int co = rem - ci * Cout;
    float v = 0.f;
    if (ci < Cin) v = wts[(co * Cin + ci) * 9 + tap];
    g_wTh[idx] = __float2half(v);
}

// ---------------- stage-1 partial conv, specialized Cin=1, Cout=80 ----------------
__launch_bounds__(256)
__global__ void pconv1_kernel(const float* __restrict__ wts,
                              const float* __restrict__ bias,
                              int H)
{
    __shared__ float s_m[3][132];
    __shared__ float s_in[3][132];
    __shared__ float s_w[9][80];

    const int t    = threadIdx.x;
    const int h    = blockIdx.x;
    const int n    = blockIdx.y;
    const int pxg  = t & 31;
    const int cog  = t >> 5;
    const int px0  = pxg * 4;
    const int lane = t & 31;

    for (int idx = t; idx < 3 * 130; idx += 256) {
        int r = idx / 130, col = idx % 130;
        int hh = h - 1 + r, ww = col - 1;
        float mv = 1.0f, dv = 0.f;
        if (hh >= 0 && hh < H && ww >= 0 && ww < W_IMG) {
            mv = g_maskA[(n * H + hh) * W_IMG + ww];
            dv = g_pool[(n * H + hh) * W_IMG + ww] * mv;
        }
        s_m[r][col]  = mv;
        s_in[r][col] = dv;
    }
    for (int idx = t; idx < 720; idx += 256)
        s_w[idx / 80][idx % 80] = wts[(idx % 80) * 9 + idx / 80];
    __syncthreads();

    float msum[4];
    #pragma unroll
    for (int p = 0; p < 4; p++) {
        float s = 0.f;
        #pragma unroll
        for (int r = 0; r < 3; r++)
            #pragma unroll
            for (int tw = 0; tw < 3; tw++)
                s += s_m[r][px0 + p + tw];
        msum[p] = s;
    }

    float acc[10][4];
    #pragma unroll
    for (int j = 0; j < 10; j++)
        #pragma unroll
        for (int p = 0; p < 4; p++) acc[j][p] = 0.f;

    #pragma unroll
    for (int r = 0; r < 3; r++) {
        float iv[6];
        #pragma unroll
        for (int k = 0; k < 6; k++) iv[k] = s_in[r][px0 + k];
        #pragma unroll
        for (int tw = 0; tw < 3; tw++) {
            #pragma unroll
            for (int j = 0; j < 10; j++) {
                float wj = s_w[r * 3 + tw][cog * 10 + j];
                #pragma unroll
                for (int p = 0; p < 4; p++)
                    acc[j][p] += wj * iv[tw + p];
            }
        }
    }

    float scale[4];
    bool  nov[4];
    #pragma unroll
    for (int p = 0; p < 4; p++) {
        float valid = msum[p];
        nov[p]   = (valid <= 0.f);
        scale[p] = 9.0f / fmaxf(valid, 1.0f);
    }
    if (cog == 0) {
        #pragma unroll
        for (int p = 0; p < 4; p++)
            g_maskB[(n * H + h) * W_IMG + px0 + p] = nov[p] ? 0.f : 1.f;
    }

    #pragma unroll
    for (int j = 0; j < 10; j++) {
        int gco = cog * 10 + j;
        float b = bias[gco];
        float ssum = 0.f, ssq = 0.f;
        #pragma unroll
        for (int p = 0; p < 4; p++) {
            float y = nov[p] ? 0.f : (acc[j][p] * scale[p] + b);
            g_convh[((size_t)(n * 80 + gco) * H + h) * W_IMG + px0 + p] = __float2half(y);
            ssum += y;
            ssq  += y * y;
        }
        #pragma unroll
        for (int off = 16; off; off >>= 1) {
            ssum += __shfl_xor_sync(0xffffffffu, ssum, off);
            ssq  += __shfl_xor_sync(0xffffffffu, ssq,  off);
        }
        if (lane == 0) {
            atomicAdd(&g_stats[gco], ssum);
            atomicAdd(&g_stats[80 + gco], ssq);
        }
    }
}

// ---------------- fp16 HMMA implicit-GEMM partial conv (R12 keeper) ----------------
// A tile per (r, ci0); taps sc=0,1,2 read at row offset sc. TAIL: last ci chunk
// of each tap is 16-wide (stage 2, Cinp=80). TAIL=false compiles branch-free.
template <bool TAIL>
__launch_bounds__(THREADS, 2)
__global__ void pconv_hmma_kernel(const float* __restrict__ bias,
                                  int Cin, int Cinp, int Cout, int H)
{
    extern __shared__ char smem[];
    const uint32_t sb = smem_u32(smem);
    float* s_m  = (float*)(smem + OFF_M);
    float* s_sc = (float*)(smem + OFF_SC);
    float* s_nv = (float*)(smem + OFF_NV);
    float* s_bi = (float*)(smem + OFF_BI);

    const int t    = threadIdx.x;
    const int wid  = t >> 5;
    const int lane = t & 31;
    const int h    = blockIdx.x % H;
    const int n    = blockIdx.x / H;
    const int co0  = blockIdx.y * NTILE;
    const int warp_m = wid & 1;
    const int warp_n = wid >> 1;

    for (int idx = t; idx < 3 * 130; idx += THREADS) {
        int r = idx / 130, col = idx % 130;
        int hh = h - 1 + r, ww = col - 1;
        float v = 1.0f;
        if (hh >= 0 && hh < H && ww >= 0 && ww < W_IMG)
            v = g_maskA[(n * H + hh) * W_IMG + ww];
        s_m[r * 132 + col] = v;
    }
    if (t < NTILE) s_bi[t] = bias[co0 + t];
    __syncthreads();

    if (t < 128) {
        float s = 0.f;
        #pragma unroll
        for (int r = 0; r < 3; r++)
            #pragma unroll
            for (int tw = 0; tw < 3; tw++)
                s += s_m[r * 132 + t + tw];
        float valid = (float)Cin * s;
        s_nv[t] = (valid <= 0.f) ? 1.f : 0.f;
        s_sc[t] = (float)(Cin * 9) / fmaxf(valid, 1.0f);
        if (blockIdx.y == 0)
            g_maskB[(n * H + h) * W_IMG + t] = (valid <= 0.f) ? 0.f : 1.f;
    }
    __syncthreads();

    const int CPT = (Cinp + 31) >> 5;   // ci chunks per tap (last may be 16 when TAIL)
    const int chunks = 9 * CPT;         // (r, j, sc) with sc fastest

    auto issue = [&](int c) {
        int sc = c % 3;
        int rem = c / 3;
        int j = rem % CPT;
        int r = rem / CPT;
        int ci0 = j << 5;
        int tap = r * 3 + sc;
        const bool is16 = TAIL && (j == CPT - 1);
        const __half* wsrc = g_wTh + ((size_t)tap * Cinp + ci0) * Cout + co0;
        const uint32_t bbase = sb + OFF_B + (c % 3) * BBUF;
        if (!is16) {
            #pragma unroll
            for (int i = 0; i < 2; i++) {
                int op = t + i * THREADS;
                int k = op / 20, seg = op - k * 20;
                cpa16(bbase + k * LDB * 2 + seg * 16, wsrc + (size_t)k * Cout + seg * 8, 16u);
            }
        } else {
            int k = t / 20, seg = t - (t / 20) * 20;
            if (k < 16)
                cpa16(bbase + k * LDB * 2 + seg * 16, wsrc + (size_t)k * Cout + seg * 8, 16u);
        }
        if (sc == 0) {
            int hh = h - 1 + r;
            bool hok = (hh >= 0 && hh < H);
            const uint32_t abase = sb + OFF_A + (rem & 1) * ABUF;
            if (!is16) {
                // A: 132 rows x 4 segs = 528 ops
                #pragma unroll
                for (int i = 0; i < 2; i++) {
                    int op = t + i * THREADS;
                    if (op < 528) {
                        int p = op >> 2, seg = op & 3;
                        int ww = p - 1;
                        bool ok = hok && ((unsigned)ww < W_IMG);
                        const __half* src = ok
                            ? &g_xmh[((size_t)(n * H + hh) * W_IMG + ww) * Cinp + ci0 + seg * 8]
                            : g_xmh;
                        cpa16(abase + (p * LDA + seg * 8) * 2, src, ok ? 16u : 0u);
                    }
                }
            } else {
                // A: 132 rows x 2 segs = 264 ops
                if (t < 264) {
                    int p = t >> 1, seg = t & 1;
                    int ww = p - 1;
                    bool ok = hok && ((unsigned)ww < W_IMG);
                    const __half* src = ok
                        ? &g_xmh[((size_t)(n * H + hh) * W_IMG + ww) * Cinp + ci0 + seg * 8]
                        : g_xmh;
                    cpa16(abase + (p * LDA + seg * 8) * 2, src, ok ? 16u : 0u);
                }
            }
        }
        CP_COMMIT();
    };

    float acc[4][4][4];
    #pragma unroll
    for (int mi = 0; mi < 4; mi++)
        #pragma unroll
        for (int ni = 0; ni < 4; ni++)
            #pragma unroll
            for (int q = 0; q < 4; q++) acc[mi][ni][q] = 0.f;

    const int rowX = lane & 15;
    const int colA = (lane >> 4) << 3;
    const uint32_t a_rel = ((warp_m * 64 + rowX) * LDA + colA) * 2;
    const uint32_t b_rel = (rowX * LDB + warp_n * 32) * 2;

    issue(0);
    if (chunks > 1) issue(1);

    for (int c = 0; c < chunks; c++) {
        CP_WAIT1();
        __syncthreads();          // single barrier per chunk
        if (c + 2 < chunks) issue(c + 2);

        const int sc = c % 3;
        const int rem = c / 3;
        const uint32_t abase = sb + OFF_A + (rem & 1) * ABUF + sc * LDA * 2 + a_rel;
        const uint32_t bbase = sb + OFF_B + (c % 3) * BBUF + b_rel;
        const int kmax = (TAIL && (rem % CPT == CPT - 1)) ? 1 : 2;

        #pragma unroll
        for (int kk = 0; kk < 2; kk++) {
            if (!TAIL || kk < kmax) {
                uint32_t a[4][4];
                #pragma unroll
                for (int mi = 0; mi < 4; mi++)
                    LDMX4(a[mi][0], a[mi][1], a[mi][2], a[mi][3],
                          abase + (mi * 16 * LDA + kk * 16) * 2);
                uint32_t b[4][2];
                #pragma unroll
                for (int ni = 0; ni < 4; ni++)
                    LDMX2T(b[ni][0], b[ni][1],
                           bbase + (kk * 16 * LDB + ni * 8) * 2);
                #pragma unroll
                for (int mi = 0; mi < 4; mi++)
                    #pragma unroll
                    for (int ni = 0; ni < 4; ni++)
                        MMA16816(acc[mi][ni], a[mi], b[ni]);
            }
        }
    }
    __syncthreads();

    // ---- epilogue: scale/bias/zero + fp16 stores + stats ----
    const int gr = lane >> 2;
    const int gc = (lane & 3) * 2;
    float ssum[4][2], ssq[4][2];
    #pragma unroll
    for (int ni = 0; ni < 4; ni++)
        #pragma unroll
        for (int q = 0; q < 2; q++) { ssum[ni][q] = 0.f; ssq[ni][q] = 0.f; }

    #pragma unroll
    for (int mi = 0; mi < 4; mi++) {
        int m0 = warp_m * 64 + mi * 16 + gr;
        int m1 = m0 + 8;
        float sc0 = s_sc[m0], sc1 = s_sc[m1];
        bool nv0 = (s_nv[m0] != 0.f), nv1 = (s_nv[m1] != 0.f);
        #pragma unroll
        for (int ni = 0; ni < 4; ni++) {
            int colb = warp_n * 32 + ni * 8 + gc;
            #pragma unroll
            for (int q = 0; q < 2; q++) {
                int col = colb + q;
                int co = co0 + col;
                float bb = s_bi[col];
                float y0 = nv0 ? 0.f : fmaf(acc[mi][ni][q], sc0, bb);
                float y1 = nv1 ? 0.f : fmaf(acc[mi][ni][2 + q], sc1, bb);
                size_t base = ((size_t)(n * Cout + co) * H + h) * W_IMG;
                g_convh[base + m0] = __float2half(y0);
                g_convh[base + m1] = __float2half(y1);
                ssum[ni][q] += y0 + y1;
                ssq[ni][q]  += y0 * y0 + y1 * y1;
            }
        }
    }
    #pragma unroll
    for (int ni = 0; ni < 4; ni++)
        #pragma unroll
        for (int q = 0; q < 2; q++) {
            float ss = ssum[ni][q], sq = ssq[ni][q];
            #pragma unroll
            for (int off = 4; off <= 16; off <<= 1) {
                ss += __shfl_xor_sync(0xffffffffu, ss, off);
                sq += __shfl_xor_sync(0xffffffffu, sq, off);
            }
            if (lane < 4) {
                int co = co0 + warp_n * 32 + ni * 8 + lane * 2 + q;
                atomicAdd(&g_stats[co], ss);
                atomicAdd(&g_stats[Cout + co], sq);
            }
        }
}

// ---------------- fused BN+ReLU+pool+premask+transpose+fp16: conv -> g_xmh ----------------
__global__ void bnx_kernel(const float* __restrict__ gamma,
                           const float* __restrict__ beta,
                           int Cout, int Hc, int Cinp)
{
    __shared__ __half tile[32][33];
    int Hp = Hc >> 1;
    int nhp = blockIdx.z;
    int n = nhp / Hp, hp = nhp % Hp;
    int w0 = blockIdx.x * 32, c0 = blockIdx.y * 32;
    int tx = threadIdx.x, ty = threadIdx.y;

    float m = g_maskA[nhp * W_IMG + w0 + tx];
    float cnt = (float)(NB * Hc * W_IMG);

    #pragma unroll
    for (int j = 0; j < 4; j++) {
        int cl = ty + j * 8;
        int c = c0 + cl;
        float y = 0.f;
        if (c < Cout) {
            float mean = g_stats[c] / cnt;
            float var  = g_stats[Cout + c] / cnt - mean * mean;
            float inv  = rsqrtf(var + 1e-5f);
            float ga = gamma[c], bb = beta[c];
            size_t base = ((size_t)(n * Cout + c) * Hc + 2 * hp) * W_IMG + w0 + tx;
            float v0 = __half2float(g_convh[base]);
            float v1 = __half2float(g_convh[base + W_IMG]);
            float r0 = fmaxf((v0 - mean) * inv * ga + bb, 0.f);
            float r1 = fmaxf((v1 - mean) * inv * ga + bb, 0.f);
            y = fmaxf(r0, r1) * m;
        }
        tile[cl][tx] = __float2half(y);
    }
    __syncthreads();
    if (c0 + tx < Cinp) {
        #pragma unroll
        for (int j = 0; j < 4; j++) {
            int wl = ty + j * 8;
            g_xmh[((size_t)nhp * W_IMG + w0 + wl) * Cinp + c0 + tx] = tile[tx][wl];
        }
    }
}

// ---------------- fused stage-4 BN+ReLU+pool+mean -> g_feat ----------------
__global__ void bnfeat_kernel(const float* __restrict__ gamma,
                              const float* __restrict__ beta,
                              int Cout, int Hc)
{
    __shared__ float sred[128];
    int c = blockIdx.x % Cout;
    int n = blockIdx.x / Cout;
    int t = threadIdx.x;
    int Hp = Hc >> 1;

    float cnt  = (float)(NB * Hc * W_IMG);
    float mean = g_stats[c] / cnt;
    float var  = g_stats[Cout + c] / cnt - mean * mean;
    float inv  = rsqrtf(var + 1e-5f);
    float ga = gamma[c], bb = beta[c];

    float s = 0.f;
    for (int i = t; i < Hp * W_IMG; i += 128) {
        int hp = i >> 7, w = i & 127;
        size_t base = ((size_t)(n * Cout + c) * Hc + 2 * hp) * W_IMG + w;
        float v0 = __half2float(g_convh[base]);
        float v1 = __half2float(g_convh[base + W_IMG]);
        float r0 = fmaxf((v0 - mean) * inv * ga + bb, 0.f);
        float r1 = fmaxf((v1 - mean) * inv * ga + bb, 0.f);
        s += fmaxf(r0, r1);
    }
    sred[t] = s;
    __syncthreads();
    for (int o = 64; o; o >>= 1) {
        if (t < o) sred[t] += sred[t + o];
        __syncthreads();
    }
    if (t == 0) g_feat[n * Cout + c] = sred[0] / (float)(Hp * W_IMG);
}

__global__ void mask_pool_kernel(int Hc) {
    int idx = blockIdx.x * blockDim.x + threadIdx.x;
    int Hp = Hc >> 1;
    int total = NB * Hp * W_IMG;
    if (idx >= total) return;
    int w  = idx % W_IMG;
    int hp = (idx / W_IMG) % Hp;
    int n  = idx / (W_IMG * Hp);
    int base = (n * Hc + 2 * hp) * W_IMG + w;
    g_maskA[(n * Hp + hp) * W_IMG + w] = fmaxf(g_maskB[base], g_maskB[base + W_IMG]);
}

// ---------------- head ----------------
__global__ void fc_kernel(const float* __restrict__ Wm, const float* __restrict__ b,
                          const float* __restrict__ in, float* __restrict__ out,
                          int IN, int OUT, int act)
{
    __shared__ float s[640];
    int n = blockIdx.x;
    for (int i = threadIdx.x; i < IN; i += blockDim.x) s[i] = in[n * IN + i];
    __syncthreads();
    int o = threadIdx.x;
    if (o < OUT) {
        float a = b[o];
        const float* wr = Wm + o * IN;
        for (int k = 0; k < IN; k++) a += wr[k] * s[k];
        if (act == 0) a = fmaxf(a, 0.f);
        else          a = 1.f / (1.f + expf(-a));
        out[n * OUT + o] = a;
    }
}

// ---------------- launch ----------------
extern "C" void kernel_launch(void* const* d_in, const int* in_sizes, int n_in,
                              void* d_out, int out_size)
{
    const float* x = (const float*)d_in[0];
    const float* w[4]  = {(const float*)d_in[1],  (const float*)d_in[5],
                          (const float*)d_in[9],  (const float*)d_in[13]};
    const float* bi[4] = {(const float*)d_in[2],  (const float*)d_in[6],
                          (const float*)d_in[10], (const float*)d_in[14]};
    const float* ga[4] = {(const float*)d_in[3],  (const float*)d_in[7],
                          (const float*)d_in[11], (const float*)d_in[15]};
    const float* be[4] = {(const float*)d_in[4],  (const float*)d_in[8],
                          (const float*)d_in[12], (const float*)d_in[16]};
    const float* fw1 = (const float*)d_in[17];
    const float* fb1 = (const float*)d_in[18];
    const float* fw2 = (const float*)d_in[19];
    const float* fb2 = (const float*)d_in[20];
    const float* hw  = (const float*)d_in[21];
    const float* hb  = (const float*)d_in[22];

    cudaFuncSetAttribute(pconv_hmma_kernel<true>,
                         cudaFuncAttributeMaxDynamicSharedMemorySize, SM_TOT);
    cudaFuncSetAttribute(pconv_hmma_kernel<false>,
                         cudaFuncAttributeMaxDynamicSharedMemorySize, SM_TOT);

    float *feat, *z1, *z2;
    cudaGetSymbolAddress((void**)&feat, g_feat);
    cudaGetSymbolAddress((void**)&z1,   g_z1);
    cudaGetSymbolAddress((void**)&z2,   g_z2);

    prep_kernel<<<(NB * 256 * 128 + 255) / 256, 256>>>(x);

    // ---- stage 1: specialized Cin=1 -> fused bnx into g_xmh (Cinp=80, exact) ----
    {
        int Cout = 80, H = 256, Hp = 128;
        zero_stats_kernel<<<1, 256>>>(2 * Cout);
        dim3 grid(H, NB);
        pconv1_kernel<<<grid, 256>>>(w[0], bi[0], H);
        mask_pool_kernel<<<(NB * Hp * W_IMG + 255) / 256, 256>>>(H);
        dim3 bg(4, 3, NB * Hp);   // c0 = 0,32,64 covering 80 (store-guarded)
        bnx_kernel<<<bg, dim3(32, 8)>>>(ga[0], be[0], Cout, H, 80);
    }

    // ---- stages 2-4: fp16 HMMA implicit GEMM, exact M/N/K ----
    int Cin = 80, H = 128;
    const int Couts[3] = {160, 320, 640};
    for (int s = 0; s < 3; s++) {
        int Cout = Couts[s];
        int Cinp = (Cin + 15) & ~15;   // 80, 160, 320
        int nT = Cout / NTILE;

        int wtot = 9 * Cinp * Cout;
        wprep_kernel<<<(wtot + 255) / 256, 256>>>(w[s + 1], Cin, Cinp, Cout);
        zero_stats_kernel<<<(2 * Cout + 255) / 256, 256>>>(2 * Cout);

        dim3 grid(NB * H, nT);
        if (Cinp & 31)
            pconv_hmma_kernel<true><<<grid, THREADS, SM_TOT>>>(bi[s + 1], Cin, Cinp, Cout, H);
        else
            pconv_hmma_kernel<false><<<grid, THREADS, SM_TOT>>>(bi[s + 1], Cin, Cinp, Cout, H);

        int Hp = H / 2;
        if (s < 2) {
            mask_pool_kernel<<<(NB * Hp * W_IMG + 255) / 256, 256>>>(H);
            int CinpN = Cout;          // 160, 320 — exact
            dim3 bg(4, (CinpN + 31) / 32, NB * Hp);
            bnx_kernel<<<bg, dim3(32, 8)>>>(ga[s + 1], be[s + 1], Cout, H, CinpN);
        } else {
            bnfeat_kernel<<<NB * Cout, 128>>>(ga[s + 1], be[s + 1], Cout, H);
        }
        Cin = Cout; H = Hp;
    }

    fc_kernel<<<NB, 256>>>(fw1, fb1, feat, z1, 640, 256, 0);
    fc_kernel<<<NB, 256>>>(fw2, fb2, z1, z2, 256, 128, 0);
    fc_kernel<<<NB, 128>>>(hw, hb, z2, (float*)d_out, 128, 1, 1);
}